// round 6
// baseline (speedup 1.0000x reference)
#include <cuda_runtime.h>
#include <math.h>

// ---------------- problem constants ----------------
#define BATCH   32
#define CIN     256
#define COUT    64
#define HW      1024
#define NE      1024
#define EDIM    64
#define NROWS   32768
#define ZLEN    (BATCH*COUT*HW)   // 2097152
#define TILES   8
#define CODE_TILE 128
#define ROWS_BLK 64               // rows per argmin block

// output layout (concat, float32): z_q | loss | sampled | min_idx
#define ZQ_OFF   0
#define LOSS_OFF ((size_t)ZLEN)
#define SAMP_OFF ((size_t)ZLEN + 1)
#define MIDX_OFF ((size_t)ZLEN + 1 + NROWS)

// argmin smem: zs4[64*17] | es4[64*33] | Sz[64] | se[128] | red[256]
#define ZS_F4    (ROWS_BLK * 17)
#define ES_F4    (64 * 33)
#define SMEM_ARGMIN ((ZS_F4 + ES_F4) * 16 + ROWS_BLK * 4 + 128 * 4 + 256 * 4)

// ---------------- device scratch ----------------
__device__ __align__(16) float g_z[ZLEN];
__device__ __align__(16) float g_embi[NE * EDIM];   // pair-interleaved codebook
__device__ int   g_idx[NROWS];
__device__ float g_se[NE];
__device__ float g_loss_part[512];
__device__ float g_s_part[32 * EDIM];

// ---------------- packed f32x2 helpers (bit-exact per-lane fma.rn) ----------------
__device__ __forceinline__ unsigned long long dupf(float v) {
    unsigned long long r;
    asm("mov.b64 %0, {%1, %1};" : "=l"(r) : "r"(__float_as_uint(v)));
    return r;
}
__device__ __forceinline__ unsigned long long pack2(float a, float b) {
    unsigned long long r;
    asm("mov.b64 %0, {%1, %2};" : "=l"(r) : "r"(__float_as_uint(a)), "r"(__float_as_uint(b)));
    return r;
}
__device__ __forceinline__ void fma2(unsigned long long& d,
                                     unsigned long long a, unsigned long long b) {
    asm("fma.rn.f32x2 %0, %1, %2, %0;" : "+l"(d) : "l"(a), "l"(b));
}
__device__ __forceinline__ void unpack2(float& lo, float& hi, unsigned long long v) {
    asm("mov.b64 {%0, %1}, %2;" : "=f"(lo), "=f"(hi) : "l"(v));
}

// Replicated XLA-CPU reduce order: VF=4, IC=2, fmla, faddp-adjacent horizontal.
__device__ __forceinline__ float sumsq64_p(const float4* v4) {
    float a0=0.f,a1=0.f,a2=0.f,a3=0.f, b0=0.f,b1=0.f,b2=0.f,b3=0.f;
    #pragma unroll
    for (int t = 0; t < 8; t++) {
        float4 x = v4[2*t];
        a0 = __fmaf_rn(x.x, x.x, a0); a1 = __fmaf_rn(x.y, x.y, a1);
        a2 = __fmaf_rn(x.z, x.z, a2); a3 = __fmaf_rn(x.w, x.w, a3);
        float4 y = v4[2*t+1];
        b0 = __fmaf_rn(y.x, y.x, b0); b1 = __fmaf_rn(y.y, y.y, b1);
        b2 = __fmaf_rn(y.z, y.z, b2); b3 = __fmaf_rn(y.w, y.w, b3);
    }
    float L0 = a0 + b0, L1 = a1 + b1, L2 = a2 + b2, L3 = a3 + b3;
    return (L0 + L1) + (L2 + L3);
}

// ============================================================
// K0: codebook prep (all 256 blocks) + norms/contrastive (blocks 0-31)
// g_embi[((t*64 + q*8 + s)*64 + k)*2 + l] = emb[(t*128 + 16q + s + 8l)*64 + k]
// ============================================================
__global__ void k_prep_norms(const float* __restrict__ emb) {
    int tid = threadIdx.x;
    {
        int o = blockIdx.x * 256 + tid;
        int P = o >> 7, r = o & 127;
        int k = r >> 1, l = r & 1;
        int t = P >> 6, q = (P >> 3) & 7, s = P & 7;
        int j = t * 128 + 16 * q + s + 8 * l;
        g_embi[o] = emb[(size_t)j * EDIM + k];
    }

    if (blockIdx.x < 32) {
        __shared__ float inv_n[32];
        __shared__ float sq[4][EDIM];
        int b = blockIdx.x;

        if (tid < 32) {
            int i = b * 32 + tid;
            float v = sumsq64_p((const float4*)(emb + (size_t)i * EDIM));
            g_se[i] = v;
            inv_n[tid] = 1.0f / sqrtf(v);
        }
        __syncthreads();

        int k = tid & 63, q = tid >> 6;
        float sacc = 0.f;
        #pragma unroll
        for (int i = 0; i < 8; i++) {
            int code = q * 8 + i;
            sacc += emb[(size_t)(b * 32 + code) * EDIM + k] * inv_n[code];
        }
        sq[q][k] = sacc;
        __syncthreads();
        if (tid < EDIM)
            g_s_part[b * EDIM + tid] =
                (sq[0][tid] + sq[1][tid]) + (sq[2][tid] + sq[3][tid]);
    }
}

// ============================================================
// K1: 1x1 conv, register-tiled: 16 outputs (8 FMA2 pairs) x 4 pixels/thread.
// Bitwise Eigen order: per output single chain, c ascending, bias last.
// ============================================================
__global__ void __launch_bounds__(128) k_conv(const float* __restrict__ zin,
                                              const float* __restrict__ w,
                                              const float* __restrict__ bias) {
    __shared__ unsigned long long ws[CIN * 8];   // [c][pair u]: (w[2u][c], w[2u+1][c])
    __shared__ float bs[16];

    int tid = threadIdx.x;
    int blk = blockIdx.x;
    int b = blk >> 3, half = (blk >> 2) & 1, og = blk & 3;
    int obase = og * 16;

    for (int m = tid; m < CIN * 8; m += 128) {
        int c = m >> 3, u = m & 7;
        const float* wp = w + (size_t)(obase + 2 * u) * CIN + c;
        ws[m] = pack2(wp[0], wp[CIN]);
    }
    if (tid < 16) bs[tid] = bias[obase + tid];
    __syncthreads();

    int p0 = half * 512 + tid;
    const float* zp = zin + (size_t)b * CIN * HW + p0;

    unsigned long long acc[8][4];
    #pragma unroll
    for (int u = 0; u < 8; u++)
        #pragma unroll
        for (int j = 0; j < 4; j++) acc[u][j] = 0ULL;

    float zn[4][8];
    #pragma unroll
    for (int j = 0; j < 4; j++)
        #pragma unroll
        for (int i = 0; i < 8; i++)
            zn[j][i] = zp[(size_t)i * HW + 128 * j];

    const ulonglong2* ws2 = (const ulonglong2*)ws;
    for (int ch = 0; ch < 32; ch++) {
        float zc[4][8];
        #pragma unroll
        for (int j = 0; j < 4; j++)
            #pragma unroll
            for (int i = 0; i < 8; i++) zc[j][i] = zn[j][i];
        if (ch < 31) {
            #pragma unroll
            for (int j = 0; j < 4; j++)
                #pragma unroll
                for (int i = 0; i < 8; i++)
                    zn[j][i] = zp[(size_t)((ch + 1) * 8 + i) * HW + 128 * j];
        }
        #pragma unroll
        for (int cc = 0; cc < 8; cc++) {
            int c = ch * 8 + cc;
            unsigned long long zz[4];
            #pragma unroll
            for (int j = 0; j < 4; j++) zz[j] = dupf(zc[j][cc]);
            const ulonglong2* wrow = ws2 + c * 4;
            #pragma unroll
            for (int uu = 0; uu < 4; uu++) {
                ulonglong2 wp = wrow[uu];
                #pragma unroll
                for (int j = 0; j < 4; j++) {
                    fma2(acc[2*uu][j],     zz[j], wp.x);
                    fma2(acc[2*uu + 1][j], zz[j], wp.y);
                }
            }
        }
    }

    float* zo = g_z + (size_t)b * COUT * HW;
    #pragma unroll
    for (int u = 0; u < 8; u++) {
        int o = obase + 2 * u;
        #pragma unroll
        for (int j = 0; j < 4; j++) {
            float lo, hi;
            unpack2(lo, hi, acc[u][j]);
            zo[(size_t)o * HW + p0 + 128 * j]       = lo + bs[2*u];
            zo[(size_t)(o + 1) * HW + p0 + 128 * j] = hi + bs[2*u + 1];
        }
    }
}

// ============================================================
// K2: fused distance+argmin, 2 rows x 8 code-pairs per thread, 64 rows/block.
// d_j = fl( fl(Sz + Se_j) - 2*dot_j ), dot = in-order 64-term chain per lane.
// Sz computed in-block from zs4 (replicated chain order).
// ============================================================
__global__ void __launch_bounds__(256, 4) k_argmin(float* __restrict__ out,
                                                   const float* __restrict__ emb) {
    extern __shared__ __align__(16) char smem[];
    float4* zs4  = (float4*)smem;                  // [64][17]
    float4* es4  = zs4 + ZS_F4;                    // [64 pairs][33]
    float*  Sz_s = (float*)(es4 + ES_F4);          // [64]
    float*  se_s = Sz_s + ROWS_BLK;                // [128]
    float*  red  = se_s + 128;                     // [256]

    int tid = threadIdx.x;
    int s   = tid & 7;
    int g   = tid >> 3;                            // 0..31
    int row0 = blockIdx.x * ROWS_BLK;

    // stage 64 z rows into smem (pad stride 17 float4)
    {
        const float4* zsrc = (const float4*)(g_z + (size_t)row0 * EDIM);
        #pragma unroll
        for (int j = 0; j < 4; j++) {
            int idx = tid + 256 * j;               // 0..1023
            int r = idx >> 4, k4 = idx & 15;
            zs4[r * 17 + k4] = zsrc[idx];
        }
    }
    __syncthreads();
    if (tid < ROWS_BLK)
        Sz_s[tid] = sumsq64_p(zs4 + tid * 17);
    __syncthreads();

    float Sz0 = Sz_s[g], Sz1 = Sz_s[g + 32];

    float best0 = 3.4e38f, best1 = 3.4e38f;
    int bi0 = 0, bi1 = 0;

    const float4* gsrc = (const float4*)g_embi;

    for (int t = 0; t < TILES; t++) {
        __syncthreads();
        const float4* src = gsrc + (size_t)t * 2048;
        #pragma unroll
        for (int j = 0; j < 8; j++) {
            int idx = tid + 256 * j;
            int pr = idx >> 5, wv = idx & 31;
            es4[pr * 33 + wv] = src[idx];
        }
        if (tid < CODE_TILE) se_s[tid] = g_se[t * CODE_TILE + tid];
        __syncthreads();

        unsigned long long acc[8][2];
        #pragma unroll
        for (int q = 0; q < 8; q++) { acc[q][0] = 0ULL; acc[q][1] = 0ULL; }

        const ulonglong2* ebase = (const ulonglong2*)(es4 + s * 33);

        #pragma unroll
        for (int k4 = 0; k4 < 16; k4++) {
            float4 z0 = zs4[g * 17 + k4];
            float4 z1 = zs4[(g + 32) * 17 + k4];
            {
                unsigned long long zx0 = dupf(z0.x), zx1 = dupf(z1.x);
                unsigned long long zy0 = dupf(z0.y), zy1 = dupf(z1.y);
                #pragma unroll
                for (int q = 0; q < 8; q++) {
                    ulonglong2 e01 = ebase[q * 8 * 33 + 2 * k4];
                    fma2(acc[q][0], zx0, e01.x); fma2(acc[q][0], zy0, e01.y);
                    fma2(acc[q][1], zx1, e01.x); fma2(acc[q][1], zy1, e01.y);
                }
            }
            {
                unsigned long long zx0 = dupf(z0.z), zx1 = dupf(z1.z);
                unsigned long long zy0 = dupf(z0.w), zy1 = dupf(z1.w);
                #pragma unroll
                for (int q = 0; q < 8; q++) {
                    ulonglong2 e23 = ebase[q * 8 * 33 + 2 * k4 + 1];
                    fma2(acc[q][0], zx0, e23.x); fma2(acc[q][0], zy0, e23.y);
                    fma2(acc[q][1], zx1, e23.x); fma2(acc[q][1], zy1, e23.y);
                }
            }
        }

        #pragma unroll
        for (int q = 0; q < 8; q++) {
            int jlo = 16 * q + s, jhi = jlo + 8;
            float selo = se_s[jlo], sehi = se_s[jhi];
            float dlo, dhi;
            unpack2(dlo, dhi, acc[q][0]);
            float dv = __fmaf_rn(-2.0f, dlo, Sz0 + selo);
            if (dv < best0) { best0 = dv; bi0 = t * CODE_TILE + jlo; }
            float dw = __fmaf_rn(-2.0f, dhi, Sz0 + sehi);
            if (dw < best0) { best0 = dw; bi0 = t * CODE_TILE + jhi; }
            unpack2(dlo, dhi, acc[q][1]);
            float du = __fmaf_rn(-2.0f, dlo, Sz1 + selo);
            if (du < best1) { best1 = du; bi1 = t * CODE_TILE + jlo; }
            float dx = __fmaf_rn(-2.0f, dhi, Sz1 + sehi);
            if (dx < best1) { best1 = dx; bi1 = t * CODE_TILE + jhi; }
        }
    }

    // lexicographic merge across the 8 sub-lanes (per row)
    unsigned m = 0xffffffffu;
    #pragma unroll
    for (int off = 4; off > 0; off >>= 1) {
        float ob = __shfl_down_sync(m, best0, off, 8);
        int   oi = __shfl_down_sync(m, bi0,   off, 8);
        if (ob < best0 || (ob == best0 && oi < bi0)) { best0 = ob; bi0 = oi; }
        float pb = __shfl_down_sync(m, best1, off, 8);
        int   pi = __shfl_down_sync(m, bi1,   off, 8);
        if (pb < best1 || (pb == best1 && pi < bi1)) { best1 = pb; bi1 = pi; }
    }
    bi0 = __shfl_sync(m, bi0, 0, 8);
    bi1 = __shfl_sync(m, bi1, 0, 8);

    // epilogue per row: idx/min_idx/sampled-zero, z_q_st = fl(z + fl(e - z)), loss
    float lacc = 0.f;
    #pragma unroll
    for (int i = 0; i < 2; i++) {
        int rl = g + 32 * i;
        int row = row0 + rl;
        int bj = i ? bi1 : bi0;
        if (s == 0) {
            g_idx[row] = bj;
            out[MIDX_OFF + row] = (float)bj;
            out[SAMP_OFF + row] = 0.0f;
        }
        const float4* eb = (const float4*)(emb + (size_t)bj * EDIM) + s * 2;
        float4* outp = (float4*)(out + ZQ_OFF + (size_t)row * EDIM) + s * 2;
        #pragma unroll
        for (int q = 0; q < 2; q++) {
            float4 e = eb[q];
            float4 z = zs4[rl * 17 + s * 2 + q];
            float dx = e.x - z.x, dy = e.y - z.y, dz = e.z - z.z, dw = e.w - z.w;
            float4 o;
            o.x = z.x + dx; o.y = z.y + dy; o.z = z.z + dz; o.w = z.w + dw;
            outp[q] = o;
            lacc += dx*dx + dy*dy + dz*dz + dw*dw;
        }
    }
    red[tid] = lacc;
    __syncthreads();
    #pragma unroll
    for (int st = 128; st > 0; st >>= 1) {
        if (tid < st) red[tid] += red[tid + st];
        __syncthreads();
    }
    if (tid == 0) g_loss_part[blockIdx.x] = red[0];
}

// ============================================================
// K3: scatter + loss finalize (512 loss parts)
// ============================================================
__global__ void k_scatter(float* __restrict__ out) {
    int tid = threadIdx.x;
    int t = blockIdx.x * 256 + tid;
    out[SAMP_OFF + g_idx[t]] = 1.0f;

    if (blockIdx.x == 0) {
        __shared__ double rd[256];
        __shared__ float sv[EDIM];
        rd[tid] = (double)g_loss_part[tid] + (double)g_loss_part[tid + 256];
        if (tid < EDIM) {
            float v = 0.f;
            #pragma unroll
            for (int j = 0; j < 32; j++) v += g_s_part[j * EDIM + tid];
            sv[tid] = v * v;
        }
        __syncthreads();
        #pragma unroll
        for (int st = 128; st > 0; st >>= 1) {
            if (tid < st) rd[tid] += rd[tid + st];
            __syncthreads();
        }
        if (tid == 0) {
            float c = 0.f;
            for (int j = 0; j < EDIM; j++) c += sv[j];
            out[LOSS_OFF] = (float)(1.25 * (rd[0] / (double)ZLEN))
                          + c / ((float)NE * (float)NE);
        }
    }
}

// ============================================================
extern "C" void kernel_launch(void* const* d_in, const int* in_sizes, int n_in,
                              void* d_out, int out_size) {
    const float* z_    = (const float*)d_in[0];
    const float* convw = (const float*)d_in[1];
    const float* convb = (const float*)d_in[2];
    const float* emb   = (const float*)d_in[3];
    float* out = (float*)d_out;

    cudaFuncSetAttribute(k_argmin, cudaFuncAttributeMaxDynamicSharedMemorySize,
                         SMEM_ARGMIN);

    k_prep_norms<<<256, 256>>>(emb);
    k_conv<<<256, 128>>>(z_, convw, convb);
    k_argmin<<<512, 256, SMEM_ARGMIN>>>(out, emb);
    k_scatter<<<128, 256>>>(out);
}

// round 7
// speedup vs baseline: 1.3971x; 1.3971x over previous
#include <cuda_runtime.h>
#include <math.h>

// ---------------- problem constants ----------------
#define BATCH   32
#define CIN     256
#define COUT    64
#define HW      1024
#define NE      1024
#define EDIM    64
#define NROWS   32768
#define ZLEN    (BATCH*COUT*HW)   // 2097152
#define TILES   8
#define CODE_TILE 128
#define ROWS_BLK 128              // rows per argmin block
#define NBLK    (NROWS / ROWS_BLK)   // 256

// output layout (concat, float32): z_q | loss | sampled | min_idx
#define ZQ_OFF   0
#define LOSS_OFF ((size_t)ZLEN)
#define SAMP_OFF ((size_t)ZLEN + 1)
#define MIDX_OFF ((size_t)ZLEN + 1 + NROWS)

// argmin smem: zs4[128*17] | es4[64*33] | Sz[128] | se[128] | red[256]
#define ZS_F4    (ROWS_BLK * 17)
#define ES_F4    (64 * 33)
#define SMEM_ARGMIN ((ZS_F4 + ES_F4) * 16 + ROWS_BLK * 4 + 128 * 4 + 256 * 4)

// ---------------- device scratch ----------------
__device__ __align__(16) float g_z[ZLEN];
__device__ __align__(16) float g_embi[NE * EDIM];   // pair-interleaved codebook
__device__ int   g_idx[NROWS];
__device__ float g_se[NE];
__device__ float g_loss_part[NBLK];
__device__ float g_s_part[32 * EDIM];

// ---------------- packed f32x2 helpers (bit-exact per-lane fma.rn) ----------------
__device__ __forceinline__ unsigned long long dupf(float v) {
    unsigned long long r;
    asm("mov.b64 %0, {%1, %1};" : "=l"(r) : "r"(__float_as_uint(v)));
    return r;
}
__device__ __forceinline__ unsigned long long pack2(float a, float b) {
    unsigned long long r;
    asm("mov.b64 %0, {%1, %2};" : "=l"(r) : "r"(__float_as_uint(a)), "r"(__float_as_uint(b)));
    return r;
}
__device__ __forceinline__ void fma2(unsigned long long& d,
                                     unsigned long long a, unsigned long long b) {
    asm("fma.rn.f32x2 %0, %1, %2, %0;" : "+l"(d) : "l"(a), "l"(b));
}
__device__ __forceinline__ void unpack2(float& lo, float& hi, unsigned long long v) {
    asm("mov.b64 {%0, %1}, %2;" : "=f"(lo), "=f"(hi) : "l"(v));
}

// Replicated XLA-CPU reduce order: VF=4, IC=2, fmla, faddp-adjacent horizontal.
__device__ __forceinline__ float sumsq64_p(const float4* v4) {
    float a0=0.f,a1=0.f,a2=0.f,a3=0.f, b0=0.f,b1=0.f,b2=0.f,b3=0.f;
    #pragma unroll
    for (int t = 0; t < 8; t++) {
        float4 x = v4[2*t];
        a0 = __fmaf_rn(x.x, x.x, a0); a1 = __fmaf_rn(x.y, x.y, a1);
        a2 = __fmaf_rn(x.z, x.z, a2); a3 = __fmaf_rn(x.w, x.w, a3);
        float4 y = v4[2*t+1];
        b0 = __fmaf_rn(y.x, y.x, b0); b1 = __fmaf_rn(y.y, y.y, b1);
        b2 = __fmaf_rn(y.z, y.z, b2); b3 = __fmaf_rn(y.w, y.w, b3);
    }
    float L0 = a0 + b0, L1 = a1 + b1, L2 = a2 + b2, L3 = a3 + b3;
    return (L0 + L1) + (L2 + L3);
}

// ============================================================
// K0: codebook prep (all 256 blocks) + norms/contrastive (blocks 0-31)
// Pair layout: tile t, smem row r = q*16 + s holds codes
// (jlo, jhi) = (t*128 + 8s + 2q, +1), element-interleaved by k:
// g_embi[((t*64 + q*16 + s)*64 + k)*2 + l] = emb[(t*128 + 8s + 2q + l)*64 + k]
// ============================================================
__global__ void k_prep_norms(const float* __restrict__ emb) {
    int tid = threadIdx.x;
    {
        int o = blockIdx.x * 256 + tid;
        int P = o >> 7, r = o & 127;
        int k = r >> 1, l = r & 1;
        int t = P >> 6, rem = P & 63;
        int q = rem >> 4, s = rem & 15;
        int j = t * 128 + 8 * s + 2 * q + l;
        g_embi[o] = emb[(size_t)j * EDIM + k];
    }

    if (blockIdx.x < 32) {
        __shared__ float inv_n[32];
        __shared__ float sq[4][EDIM];
        int b = blockIdx.x;

        if (tid < 32) {
            int i = b * 32 + tid;
            float v = sumsq64_p((const float4*)(emb + (size_t)i * EDIM));
            g_se[i] = v;
            inv_n[tid] = 1.0f / sqrtf(v);
        }
        __syncthreads();

        int k = tid & 63, q = tid >> 6;
        float sacc = 0.f;
        #pragma unroll
        for (int i = 0; i < 8; i++) {
            int code = q * 8 + i;
            sacc += emb[(size_t)(b * 32 + code) * EDIM + k] * inv_n[code];
        }
        sq[q][k] = sacc;
        __syncthreads();
        if (tid < EDIM)
            g_s_part[b * EDIM + tid] =
                (sq[0][tid] + sq[1][tid]) + (sq[2][tid] + sq[3][tid]);
    }
}

// ============================================================
// K1: 1x1 conv, register-tiled: 16 outputs (8 FMA2 pairs) x 4 pixels/thread.
// Bitwise Eigen order: per output single chain, c ascending, bias last.
// ============================================================
__global__ void __launch_bounds__(128) k_conv(const float* __restrict__ zin,
                                              const float* __restrict__ w,
                                              const float* __restrict__ bias) {
    __shared__ unsigned long long ws[CIN * 8];   // [c][pair u]: (w[2u][c], w[2u+1][c])
    __shared__ float bs[16];

    int tid = threadIdx.x;
    int blk = blockIdx.x;
    int b = blk >> 3, half = (blk >> 2) & 1, og = blk & 3;
    int obase = og * 16;

    for (int m = tid; m < CIN * 8; m += 128) {
        int c = m >> 3, u = m & 7;
        const float* wp = w + (size_t)(obase + 2 * u) * CIN + c;
        ws[m] = pack2(wp[0], wp[CIN]);
    }
    if (tid < 16) bs[tid] = bias[obase + tid];
    __syncthreads();

    int p0 = half * 512 + tid;
    const float* zp = zin + (size_t)b * CIN * HW + p0;

    unsigned long long acc[8][4];
    #pragma unroll
    for (int u = 0; u < 8; u++)
        #pragma unroll
        for (int j = 0; j < 4; j++) acc[u][j] = 0ULL;

    float zn[4][8];
    #pragma unroll
    for (int j = 0; j < 4; j++)
        #pragma unroll
        for (int i = 0; i < 8; i++)
            zn[j][i] = zp[(size_t)i * HW + 128 * j];

    const ulonglong2* ws2 = (const ulonglong2*)ws;
    for (int ch = 0; ch < 32; ch++) {
        float zc[4][8];
        #pragma unroll
        for (int j = 0; j < 4; j++)
            #pragma unroll
            for (int i = 0; i < 8; i++) zc[j][i] = zn[j][i];
        if (ch < 31) {
            #pragma unroll
            for (int j = 0; j < 4; j++)
                #pragma unroll
                for (int i = 0; i < 8; i++)
                    zn[j][i] = zp[(size_t)((ch + 1) * 8 + i) * HW + 128 * j];
        }
        #pragma unroll
        for (int cc = 0; cc < 8; cc++) {
            int c = ch * 8 + cc;
            unsigned long long zz[4];
            #pragma unroll
            for (int j = 0; j < 4; j++) zz[j] = dupf(zc[j][cc]);
            const ulonglong2* wrow = ws2 + c * 4;
            #pragma unroll
            for (int uu = 0; uu < 4; uu++) {
                ulonglong2 wp = wrow[uu];
                #pragma unroll
                for (int j = 0; j < 4; j++) {
                    fma2(acc[2*uu][j],     zz[j], wp.x);
                    fma2(acc[2*uu + 1][j], zz[j], wp.y);
                }
            }
        }
    }

    float* zo = g_z + (size_t)b * COUT * HW;
    #pragma unroll
    for (int u = 0; u < 8; u++) {
        int o = obase + 2 * u;
        #pragma unroll
        for (int j = 0; j < 4; j++) {
            float lo, hi;
            unpack2(lo, hi, acc[u][j]);
            zo[(size_t)o * HW + p0 + 128 * j]       = lo + bs[2*u];
            zo[(size_t)(o + 1) * HW + p0 + 128 * j] = hi + bs[2*u + 1];
        }
    }
}

// ============================================================
// K2: fused distance+argmin: 8 rows x 4 code-pairs per thread,
// 128 rows/block, 16 sublanes per row. Conflict-free e layout.
// d_j = fl( fl(Sz + Se_j) - 2*dot_j ), dot = in-order 64-term chain per lane.
// ============================================================
__global__ void __launch_bounds__(256, 2) k_argmin(float* __restrict__ out,
                                                   const float* __restrict__ emb) {
    extern __shared__ __align__(16) char smem[];
    float4* zs4  = (float4*)smem;                  // [128][17]
    float4* es4  = zs4 + ZS_F4;                    // [64 pair-rows][33]
    float*  Sz_s = (float*)(es4 + ES_F4);          // [128]
    float*  se_s = Sz_s + ROWS_BLK;                // [128]
    float*  red  = se_s + 128;                     // [256]

    int tid = threadIdx.x;
    int s   = tid & 15;                            // sublane 0..15
    int g   = tid >> 4;                            // row group 0..15
    int row0 = blockIdx.x * ROWS_BLK;

    // stage 128 z rows into smem (pad stride 17 float4)
    {
        const float4* zsrc = (const float4*)(g_z + (size_t)row0 * EDIM);
        #pragma unroll
        for (int j = 0; j < 8; j++) {
            int idx = tid + 256 * j;               // 0..2047
            int r = idx >> 4, k4 = idx & 15;
            zs4[r * 17 + k4] = zsrc[idx];
        }
    }
    __syncthreads();
    if (tid < ROWS_BLK)
        Sz_s[tid] = sumsq64_p(zs4 + tid * 17);
    __syncthreads();

    float best[8];
    int   bi[8];
    #pragma unroll
    for (int i = 0; i < 8; i++) { best[i] = 3.4e38f; bi[i] = 0; }

    const float4* gsrc = (const float4*)g_embi;
    const float2* zb = ((const float2*)zs4) + g * 34;        // row g, float2 units
    const ulonglong2* ebase = ((const ulonglong2*)es4) + s * 33;

    for (int t = 0; t < TILES; t++) {
        __syncthreads();
        const float4* src = gsrc + (size_t)t * 2048;
        #pragma unroll
        for (int j = 0; j < 8; j++) {
            int idx = tid + 256 * j;
            int pr = idx >> 5, wv = idx & 31;
            es4[pr * 33 + wv] = src[idx];
        }
        if (tid < CODE_TILE) se_s[tid] = g_se[t * CODE_TILE + tid];
        __syncthreads();

        unsigned long long acc[8][4];
        #pragma unroll
        for (int i = 0; i < 8; i++)
            #pragma unroll
            for (int q = 0; q < 4; q++) acc[i][q] = 0ULL;

        #pragma unroll 4
        for (int k4 = 0; k4 < 16; k4++) {
            unsigned long long zx[8], zy[8];
            // half A: dims 4k4, 4k4+1
            #pragma unroll
            for (int i = 0; i < 8; i++) {
                float2 h = zb[544 * i + 2 * k4];
                zx[i] = dupf(h.x); zy[i] = dupf(h.y);
            }
            #pragma unroll
            for (int q = 0; q < 4; q++) {
                ulonglong2 e01 = ebase[q * 528 + 2 * k4];
                #pragma unroll
                for (int i = 0; i < 8; i++) {
                    fma2(acc[i][q], zx[i], e01.x);
                    fma2(acc[i][q], zy[i], e01.y);
                }
            }
            // half B: dims 4k4+2, 4k4+3
            #pragma unroll
            for (int i = 0; i < 8; i++) {
                float2 h = zb[544 * i + 2 * k4 + 1];
                zx[i] = dupf(h.x); zy[i] = dupf(h.y);
            }
            #pragma unroll
            for (int q = 0; q < 4; q++) {
                ulonglong2 e23 = ebase[q * 528 + 2 * k4 + 1];
                #pragma unroll
                for (int i = 0; i < 8; i++) {
                    fma2(acc[i][q], zx[i], e23.x);
                    fma2(acc[i][q], zy[i], e23.y);
                }
            }
        }

        // eval: per row, q ascending -> codes 8s+2q, 8s+2q+1 ascending
        #pragma unroll
        for (int q = 0; q < 4; q++) {
            int jlo = 8 * s + 2 * q, jhi = jlo + 1;
            float selo = se_s[jlo], sehi = se_s[jhi];
            #pragma unroll
            for (int i = 0; i < 8; i++) {
                float Szv = Sz_s[g + 16 * i];
                float dlo, dhi;
                unpack2(dlo, dhi, acc[i][q]);
                float dv = __fmaf_rn(-2.0f, dlo, Szv + selo);
                if (dv < best[i]) { best[i] = dv; bi[i] = t * CODE_TILE + jlo; }
                float dw = __fmaf_rn(-2.0f, dhi, Szv + sehi);
                if (dw < best[i]) { best[i] = dw; bi[i] = t * CODE_TILE + jhi; }
            }
        }
    }

    // lexicographic merge across the 16 sublanes (per row)
    unsigned m = 0xffffffffu;
    #pragma unroll
    for (int i = 0; i < 8; i++) {
        float bv = best[i]; int bj = bi[i];
        #pragma unroll
        for (int off = 8; off > 0; off >>= 1) {
            float ob = __shfl_down_sync(m, bv, off, 16);
            int   oi = __shfl_down_sync(m, bj, off, 16);
            if (ob < bv || (ob == bv && oi < bj)) { bv = ob; bj = oi; }
        }
        bj = __shfl_sync(m, bj, 0, 16);
        bi[i] = bj;
    }

    // epilogue per row: idx/min_idx/sampled-zero, z_q_st = fl(z + fl(e - z)), loss
    float lacc = 0.f;
    #pragma unroll
    for (int i = 0; i < 8; i++) {
        int rl = g + 16 * i;
        int row = row0 + rl;
        int bj = bi[i];
        if (s == 0) {
            g_idx[row] = bj;
            out[MIDX_OFF + row] = (float)bj;
            out[SAMP_OFF + row] = 0.0f;
        }
        float4 e = ((const float4*)(emb + (size_t)bj * EDIM))[s];
        float4 z = zs4[rl * 17 + s];
        float dx = e.x - z.x, dy = e.y - z.y, dz = e.z - z.z, dw = e.w - z.w;
        float4 o;
        o.x = z.x + dx; o.y = z.y + dy; o.z = z.z + dz; o.w = z.w + dw;
        ((float4*)(out + ZQ_OFF + (size_t)row * EDIM))[s] = o;
        lacc += dx*dx + dy*dy + dz*dz + dw*dw;
    }
    red[tid] = lacc;
    __syncthreads();
    #pragma unroll
    for (int st = 128; st > 0; st >>= 1) {
        if (tid < st) red[tid] += red[tid + st];
        __syncthreads();
    }
    if (tid == 0) g_loss_part[blockIdx.x] = red[0];
}

// ============================================================
// K3: scatter + loss finalize (256 loss parts)
// ============================================================
__global__ void k_scatter(float* __restrict__ out) {
    int tid = threadIdx.x;
    int t = blockIdx.x * 256 + tid;
    out[SAMP_OFF + g_idx[t]] = 1.0f;

    if (blockIdx.x == 0) {
        __shared__ double rd[256];
        __shared__ float sv[EDIM];
        rd[tid] = (double)g_loss_part[tid];
        if (tid < EDIM) {
            float v = 0.f;
            #pragma unroll
            for (int j = 0; j < 32; j++) v += g_s_part[j * EDIM + tid];
            sv[tid] = v * v;
        }
        __syncthreads();
        #pragma unroll
        for (int st = 128; st > 0; st >>= 1) {
            if (tid < st) rd[tid] += rd[tid + st];
            __syncthreads();
        }
        if (tid == 0) {
            float c = 0.f;
            for (int j = 0; j < EDIM; j++) c += sv[j];
            out[LOSS_OFF] = (float)(1.25 * (rd[0] / (double)ZLEN))
                          + c / ((float)NE * (float)NE);
        }
    }
}

// ============================================================
extern "C" void kernel_launch(void* const* d_in, const int* in_sizes, int n_in,
                              void* d_out, int out_size) {
    const float* z_    = (const float*)d_in[0];
    const float* convw = (const float*)d_in[1];
    const float* convb = (const float*)d_in[2];
    const float* emb   = (const float*)d_in[3];
    float* out = (float*)d_out;

    cudaFuncSetAttribute(k_argmin, cudaFuncAttributeMaxDynamicSharedMemorySize,
                         SMEM_ARGMIN);

    k_prep_norms<<<256, 256>>>(emb);
    k_conv<<<256, 128>>>(z_, convw, convb);
    k_argmin<<<NBLK, 256, SMEM_ARGMIN>>>(out, emb);
    k_scatter<<<128, 256>>>(out);
}

// round 8
// speedup vs baseline: 1.5099x; 1.0807x over previous
#include <cuda_runtime.h>
#include <math.h>

// ---------------- problem constants ----------------
#define BATCH   32
#define CIN     256
#define COUT    64
#define HW      1024
#define NE      1024
#define EDIM    64
#define NROWS   32768
#define ZLEN    (BATCH*COUT*HW)   // 2097152
#define TILES   8
#define CODE_TILE 128
#define ROWS_BLK 112              // rows per argmin block (7 groups of 16)
#define RPT      7                // rows per thread
#define NBLK     293              // ceil(32768/112); 292*112=32704, last block 64 rows

// output layout (concat, float32): z_q | loss | sampled | min_idx
#define ZQ_OFF   0
#define LOSS_OFF ((size_t)ZLEN)
#define SAMP_OFF ((size_t)ZLEN + 1)
#define MIDX_OFF ((size_t)ZLEN + 1 + NROWS)

// argmin smem: zs4[112*17] | es4[2][64*33] | Sz[112] | se[2][128] | red[256]
#define ZS_F4    (ROWS_BLK * 17)          // 1904
#define ES_F4    (64 * 33)                // 2112 per buffer
#define SMEM_ARGMIN ((ZS_F4 + 2*ES_F4) * 16 + ROWS_BLK * 4 + 256 * 4 + 256 * 4)

// ---------------- device scratch ----------------
__device__ __align__(16) float g_z[ZLEN];
__device__ __align__(16) float g_embi[NE * EDIM];   // pair-interleaved codebook
__device__ int   g_idx[NROWS];
__device__ float g_se[NE];
__device__ float g_loss_part[NBLK];
__device__ float g_s_part[32 * EDIM];

// ---------------- packed f32x2 helpers (bit-exact per-lane fma.rn) ----------------
__device__ __forceinline__ unsigned long long dupf(float v) {
    unsigned long long r;
    asm("mov.b64 %0, {%1, %1};" : "=l"(r) : "r"(__float_as_uint(v)));
    return r;
}
__device__ __forceinline__ unsigned long long pack2(float a, float b) {
    unsigned long long r;
    asm("mov.b64 %0, {%1, %2};" : "=l"(r) : "r"(__float_as_uint(a)), "r"(__float_as_uint(b)));
    return r;
}
__device__ __forceinline__ void fma2(unsigned long long& d,
                                     unsigned long long a, unsigned long long b) {
    asm("fma.rn.f32x2 %0, %1, %2, %0;" : "+l"(d) : "l"(a), "l"(b));
}
__device__ __forceinline__ void unpack2(float& lo, float& hi, unsigned long long v) {
    asm("mov.b64 {%0, %1}, %2;" : "=f"(lo), "=f"(hi) : "l"(v));
}

// Replicated XLA-CPU reduce order: VF=4, IC=2, fmla, faddp-adjacent horizontal.
__device__ __forceinline__ float sumsq64_p(const float4* v4) {
    float a0=0.f,a1=0.f,a2=0.f,a3=0.f, b0=0.f,b1=0.f,b2=0.f,b3=0.f;
    #pragma unroll
    for (int t = 0; t < 8; t++) {
        float4 x = v4[2*t];
        a0 = __fmaf_rn(x.x, x.x, a0); a1 = __fmaf_rn(x.y, x.y, a1);
        a2 = __fmaf_rn(x.z, x.z, a2); a3 = __fmaf_rn(x.w, x.w, a3);
        float4 y = v4[2*t+1];
        b0 = __fmaf_rn(y.x, y.x, b0); b1 = __fmaf_rn(y.y, y.y, b1);
        b2 = __fmaf_rn(y.z, y.z, b2); b3 = __fmaf_rn(y.w, y.w, b3);
    }
    float L0 = a0 + b0, L1 = a1 + b1, L2 = a2 + b2, L3 = a3 + b3;
    return (L0 + L1) + (L2 + L3);
}

// ============================================================
// K0: codebook prep (all 256 blocks) + norms/contrastive (blocks 0-31)
// Pair layout: tile t, smem pair-row r = q*16 + s holds codes
// (t*128 + 8s + 2q, +1), element-interleaved by k.
// ============================================================
__global__ void k_prep_norms(const float* __restrict__ emb) {
    int tid = threadIdx.x;
    {
        int o = blockIdx.x * 256 + tid;
        int P = o >> 7, r = o & 127;
        int k = r >> 1, l = r & 1;
        int t = P >> 6, rem = P & 63;
        int q = rem >> 4, s = rem & 15;
        int j = t * 128 + 8 * s + 2 * q + l;
        g_embi[o] = emb[(size_t)j * EDIM + k];
    }

    if (blockIdx.x < 32) {
        __shared__ float inv_n[32];
        __shared__ float sq[4][EDIM];
        int b = blockIdx.x;

        if (tid < 32) {
            int i = b * 32 + tid;
            float v = sumsq64_p((const float4*)(emb + (size_t)i * EDIM));
            g_se[i] = v;
            inv_n[tid] = 1.0f / sqrtf(v);
        }
        __syncthreads();

        int k = tid & 63, q = tid >> 6;
        float sacc = 0.f;
        #pragma unroll
        for (int i = 0; i < 8; i++) {
            int code = q * 8 + i;
            sacc += emb[(size_t)(b * 32 + code) * EDIM + k] * inv_n[code];
        }
        sq[q][k] = sacc;
        __syncthreads();
        if (tid < EDIM)
            g_s_part[b * EDIM + tid] =
                (sq[0][tid] + sq[1][tid]) + (sq[2][tid] + sq[3][tid]);
    }
}

// ============================================================
// K1: 1x1 conv, register-tiled: 16 outputs (8 FMA2 pairs) x 4 pixels/thread.
// Bitwise Eigen order: per output single chain, c ascending, bias last.
// ============================================================
__global__ void __launch_bounds__(128) k_conv(const float* __restrict__ zin,
                                              const float* __restrict__ w,
                                              const float* __restrict__ bias) {
    __shared__ unsigned long long ws[CIN * 8];
    __shared__ float bs[16];

    int tid = threadIdx.x;
    int blk = blockIdx.x;
    int b = blk >> 3, half = (blk >> 2) & 1, og = blk & 3;
    int obase = og * 16;

    for (int m = tid; m < CIN * 8; m += 128) {
        int c = m >> 3, u = m & 7;
        const float* wp = w + (size_t)(obase + 2 * u) * CIN + c;
        ws[m] = pack2(wp[0], wp[CIN]);
    }
    if (tid < 16) bs[tid] = bias[obase + tid];
    __syncthreads();

    int p0 = half * 512 + tid;
    const float* zp = zin + (size_t)b * CIN * HW + p0;

    unsigned long long acc[8][4];
    #pragma unroll
    for (int u = 0; u < 8; u++)
        #pragma unroll
        for (int j = 0; j < 4; j++) acc[u][j] = 0ULL;

    float zn[4][8];
    #pragma unroll
    for (int j = 0; j < 4; j++)
        #pragma unroll
        for (int i = 0; i < 8; i++)
            zn[j][i] = zp[(size_t)i * HW + 128 * j];

    const ulonglong2* ws2 = (const ulonglong2*)ws;
    for (int ch = 0; ch < 32; ch++) {
        float zc[4][8];
        #pragma unroll
        for (int j = 0; j < 4; j++)
            #pragma unroll
            for (int i = 0; i < 8; i++) zc[j][i] = zn[j][i];
        if (ch < 31) {
            #pragma unroll
            for (int j = 0; j < 4; j++)
                #pragma unroll
                for (int i = 0; i < 8; i++)
                    zn[j][i] = zp[(size_t)((ch + 1) * 8 + i) * HW + 128 * j];
        }
        #pragma unroll
        for (int cc = 0; cc < 8; cc++) {
            int c = ch * 8 + cc;
            unsigned long long zz[4];
            #pragma unroll
            for (int j = 0; j < 4; j++) zz[j] = dupf(zc[j][cc]);
            const ulonglong2* wrow = ws2 + c * 4;
            #pragma unroll
            for (int uu = 0; uu < 4; uu++) {
                ulonglong2 wp = wrow[uu];
                #pragma unroll
                for (int j = 0; j < 4; j++) {
                    fma2(acc[2*uu][j],     zz[j], wp.x);
                    fma2(acc[2*uu + 1][j], zz[j], wp.y);
                }
            }
        }
    }

    float* zo = g_z + (size_t)b * COUT * HW;
    #pragma unroll
    for (int u = 0; u < 8; u++) {
        int o = obase + 2 * u;
        #pragma unroll
        for (int j = 0; j < 4; j++) {
            float lo, hi;
            unpack2(lo, hi, acc[u][j]);
            zo[(size_t)o * HW + p0 + 128 * j]       = lo + bs[2*u];
            zo[(size_t)(o + 1) * HW + p0 + 128 * j] = hi + bs[2*u + 1];
        }
    }
}

// ============================================================
// K2: fused distance+argmin: 7 rows x 4 code-pairs per thread,
// 112 rows/block, grid 293 (balanced on 296 = 148x2 slots),
// double-buffered e tiles (1 sync per tile).
// d_j = fl( fl(Sz + Se_j) - 2*dot_j ), dot = in-order 64-term chain per lane.
// ============================================================
__global__ void __launch_bounds__(256, 2) k_argmin(float* __restrict__ out,
                                                   const float* __restrict__ emb) {
    extern __shared__ __align__(16) char smem[];
    float4* zs4  = (float4*)smem;                  // [112][17]
    float4* es4  = zs4 + ZS_F4;                    // [2][64 pair-rows][33]
    float*  Sz_s = (float*)(es4 + 2 * ES_F4);      // [112]
    float*  se_s = Sz_s + ROWS_BLK;                // [2][128]
    float*  red  = se_s + 256;                     // [256]

    int tid = threadIdx.x;
    int s   = tid & 15;                            // code sublane 0..15
    int g   = tid >> 4;                            // row group 0..15
    int row0 = blockIdx.x * ROWS_BLK;

    // stage 112 z rows (clamped for the last block) + e tile 0 + se tile 0
    {
        const float4* zall = (const float4*)g_z;
        #pragma unroll
        for (int j = 0; j < RPT; j++) {
            int idx = tid + 256 * j;               // 0..1791
            int r = idx >> 4, k4 = idx & 15;
            int grow = row0 + r;
            if (grow > NROWS - 1) grow = NROWS - 1;
            zs4[r * 17 + k4] = zall[(size_t)grow * 16 + k4];
        }
        const float4* src = (const float4*)g_embi;
        #pragma unroll
        for (int j = 0; j < 8; j++) {
            int idx = tid + 256 * j;
            int pr = idx >> 5, wv = idx & 31;
            es4[pr * 33 + wv] = src[idx];
        }
        if (tid < CODE_TILE) se_s[tid] = g_se[tid];
    }
    __syncthreads();
    if (tid < ROWS_BLK)
        Sz_s[tid] = sumsq64_p(zs4 + tid * 17);
    __syncthreads();

    float best[RPT];
    int   bi[RPT];
    #pragma unroll
    for (int i = 0; i < RPT; i++) { best[i] = 3.4e38f; bi[i] = 0; }

    const float4* gsrc = (const float4*)g_embi;
    const float2* zb = ((const float2*)zs4) + g * 34;

    for (int t = 0; t < TILES; t++) {
        int cur = t & 1, nxt = 1 - cur;

        // prefetch tile t+1 into the other buffer (reads of that buffer
        // finished before the sync that ended iteration t-1)
        if (t + 1 < TILES) {
            const float4* src = gsrc + (size_t)(t + 1) * 2048;
            #pragma unroll
            for (int j = 0; j < 8; j++) {
                int idx = tid + 256 * j;
                int pr = idx >> 5, wv = idx & 31;
                es4[nxt * ES_F4 + pr * 33 + wv] = src[idx];
            }
            if (tid < CODE_TILE)
                se_s[nxt * 128 + tid] = g_se[(t + 1) * CODE_TILE + tid];
        }

        unsigned long long acc[RPT][4];
        #pragma unroll
        for (int i = 0; i < RPT; i++)
            #pragma unroll
            for (int q = 0; q < 4; q++) acc[i][q] = 0ULL;

        const ulonglong2* ebase = ((const ulonglong2*)(es4 + cur * ES_F4)) + s * 33;

        #pragma unroll 4
        for (int k4 = 0; k4 < 16; k4++) {
            unsigned long long zx[RPT], zy[RPT];
            // half A: dims 4k4, 4k4+1
            #pragma unroll
            for (int i = 0; i < RPT; i++) {
                float2 h = zb[544 * i + 2 * k4];
                zx[i] = dupf(h.x); zy[i] = dupf(h.y);
            }
            #pragma unroll
            for (int q = 0; q < 4; q++) {
                ulonglong2 e01 = ebase[q * 528 + 2 * k4];
                #pragma unroll
                for (int i = 0; i < RPT; i++) {
                    fma2(acc[i][q], zx[i], e01.x);
                    fma2(acc[i][q], zy[i], e01.y);
                }
            }
            // half B: dims 4k4+2, 4k4+3
            #pragma unroll
            for (int i = 0; i < RPT; i++) {
                float2 h = zb[544 * i + 2 * k4 + 1];
                zx[i] = dupf(h.x); zy[i] = dupf(h.y);
            }
            #pragma unroll
            for (int q = 0; q < 4; q++) {
                ulonglong2 e23 = ebase[q * 528 + 2 * k4 + 1];
                #pragma unroll
                for (int i = 0; i < RPT; i++) {
                    fma2(acc[i][q], zx[i], e23.x);
                    fma2(acc[i][q], zy[i], e23.y);
                }
            }
        }

        // eval: per row, q ascending -> codes 8s+2q, 8s+2q+1 ascending
        #pragma unroll
        for (int q = 0; q < 4; q++) {
            int jlo = 8 * s + 2 * q, jhi = jlo + 1;
            float selo = se_s[cur * 128 + jlo], sehi = se_s[cur * 128 + jhi];
            #pragma unroll
            for (int i = 0; i < RPT; i++) {
                float Szv = Sz_s[g + 16 * i];
                float dlo, dhi;
                unpack2(dlo, dhi, acc[i][q]);
                float dv = __fmaf_rn(-2.0f, dlo, Szv + selo);
                if (dv < best[i]) { best[i] = dv; bi[i] = t * CODE_TILE + jlo; }
                float dw = __fmaf_rn(-2.0f, dhi, Szv + sehi);
                if (dw < best[i]) { best[i] = dw; bi[i] = t * CODE_TILE + jhi; }
            }
        }
        __syncthreads();
    }

    // lexicographic merge across the 16 sublanes (per row)
    unsigned m = 0xffffffffu;
    #pragma unroll
    for (int i = 0; i < RPT; i++) {
        float bv = best[i]; int bj = bi[i];
        #pragma unroll
        for (int off = 8; off > 0; off >>= 1) {
            float ob = __shfl_down_sync(m, bv, off, 16);
            int   oi = __shfl_down_sync(m, bj, off, 16);
            if (ob < bv || (ob == bv && oi < bj)) { bv = ob; bj = oi; }
        }
        bj = __shfl_sync(m, bj, 0, 16);
        bi[i] = bj;
    }

    // epilogue per valid row: idx/min_idx/sampled-zero,
    // z_q_st = fl(z + fl(e - z)), loss partial
    float lacc = 0.f;
    #pragma unroll
    for (int i = 0; i < RPT; i++) {
        int rl = g + 16 * i;
        int row = row0 + rl;
        if (row < NROWS) {
            int bj = bi[i];
            if (s == 0) {
                g_idx[row] = bj;
                out[MIDX_OFF + row] = (float)bj;
                out[SAMP_OFF + row] = 0.0f;
            }
            float4 e = ((const float4*)(emb + (size_t)bj * EDIM))[s];
            float4 z = zs4[rl * 17 + s];
            float dx = e.x - z.x, dy = e.y - z.y, dz = e.z - z.z, dw = e.w - z.w;
            float4 o;
            o.x = z.x + dx; o.y = z.y + dy; o.z = z.z + dz; o.w = z.w + dw;
            ((float4*)(out + ZQ_OFF + (size_t)row * EDIM))[s] = o;
            lacc += dx*dx + dy*dy + dz*dz + dw*dw;
        }
    }
    red[tid] = lacc;
    __syncthreads();
    #pragma unroll
    for (int st = 128; st > 0; st >>= 1) {
        if (tid < st) red[tid] += red[tid + st];
        __syncthreads();
    }
    if (tid == 0) g_loss_part[blockIdx.x] = red[0];
}

// ============================================================
// K3: scatter + loss finalize (293 loss parts)
// ============================================================
__global__ void k_scatter(float* __restrict__ out) {
    int tid = threadIdx.x;
    int t = blockIdx.x * 256 + tid;
    out[SAMP_OFF + g_idx[t]] = 1.0f;

    if (blockIdx.x == 0) {
        __shared__ double rd[256];
        __shared__ float sv[EDIM];
        double a = (double)g_loss_part[tid];
        if (tid < NBLK - 256) a += (double)g_loss_part[tid + 256];
        rd[tid] = a;
        if (tid < EDIM) {
            float v = 0.f;
            #pragma unroll
            for (int j = 0; j < 32; j++) v += g_s_part[j * EDIM + tid];
            sv[tid] = v * v;
        }
        __syncthreads();
        #pragma unroll
        for (int st = 128; st > 0; st >>= 1) {
            if (tid < st) rd[tid] += rd[tid + st];
            __syncthreads();
        }
        if (tid == 0) {
            float c = 0.f;
            for (int j = 0; j < EDIM; j++) c += sv[j];
            out[LOSS_OFF] = (float)(1.25 * (rd[0] / (double)ZLEN))
                          + c / ((float)NE * (float)NE);
        }
    }
}

// ============================================================
extern "C" void kernel_launch(void* const* d_in, const int* in_sizes, int n_in,
                              void* d_out, int out_size) {
    const float* z_    = (const float*)d_in[0];
    const float* convw = (const float*)d_in[1];
    const float* convb = (const float*)d_in[2];
    const float* emb   = (const float*)d_in[3];
    float* out = (float*)d_out;

    cudaFuncSetAttribute(k_argmin, cudaFuncAttributeMaxDynamicSharedMemorySize,
                         SMEM_ARGMIN);

    k_prep_norms<<<256, 256>>>(emb);
    k_conv<<<256, 128>>>(z_, convw, convb);
    k_argmin<<<NBLK, 256, SMEM_ARGMIN>>>(out, emb);
    k_scatter<<<128, 256>>>(out);
}

// round 9
// speedup vs baseline: 1.5251x; 1.0101x over previous
#include <cuda_runtime.h>
#include <math.h>

// ---------------- problem constants ----------------
#define BATCH   32
#define CIN     256
#define COUT    64
#define HW      1024
#define NE      1024
#define EDIM    64
#define NROWS   32768
#define ZLEN    (BATCH*COUT*HW)   // 2097152
#define TILES   8
#define CODE_TILE 128
#define ROWS_BLK 112              // rows per argmin block (7 groups of 16)
#define RPT      7                // rows per thread
#define NBLK     293              // ceil(32768/112)

// output layout (concat, float32): z_q | loss | sampled | min_idx
#define ZQ_OFF   0
#define LOSS_OFF ((size_t)ZLEN)
#define SAMP_OFF ((size_t)ZLEN + 1)
#define MIDX_OFF ((size_t)ZLEN + 1 + NROWS)

// argmin smem: zs4[112*17] | es4[2][64*33] | Sz[112] | se[2][128] | red[256]
#define ZS_F4    (ROWS_BLK * 17)          // 1904
#define ES_F4    (64 * 33)                // 2112 per buffer
#define SMEM_ARGMIN ((ZS_F4 + 2*ES_F4) * 16 + ROWS_BLK * 4 + 256 * 4 + 256 * 4)

// ---------------- device scratch ----------------
__device__ __align__(16) float g_z[ZLEN];
__device__ __align__(16) float g_embi[NE * EDIM];   // pair-interleaved codebook
__device__ int   g_idx[NROWS];
__device__ float g_se[NE];
__device__ float g_loss_part[NBLK];
__device__ float g_s_part[32 * EDIM];
__device__ int   g_done;

// ---------------- packed f32x2 helpers (bit-exact per-lane fma.rn) ----------------
__device__ __forceinline__ unsigned long long dupf(float v) {
    unsigned long long r;
    asm("mov.b64 %0, {%1, %1};" : "=l"(r) : "r"(__float_as_uint(v)));
    return r;
}
__device__ __forceinline__ unsigned long long pack2(float a, float b) {
    unsigned long long r;
    asm("mov.b64 %0, {%1, %2};" : "=l"(r) : "r"(__float_as_uint(a)), "r"(__float_as_uint(b)));
    return r;
}
__device__ __forceinline__ void fma2(unsigned long long& d,
                                     unsigned long long a, unsigned long long b) {
    asm("fma.rn.f32x2 %0, %1, %2, %0;" : "+l"(d) : "l"(a), "l"(b));
}
__device__ __forceinline__ void unpack2(float& lo, float& hi, unsigned long long v) {
    asm("mov.b64 {%0, %1}, %2;" : "=f"(lo), "=f"(hi) : "l"(v));
}

// Replicated XLA-CPU reduce order: VF=4, IC=2, fmla, faddp-adjacent horizontal.
__device__ __forceinline__ float sumsq64_p(const float4* v4) {
    float a0=0.f,a1=0.f,a2=0.f,a3=0.f, b0=0.f,b1=0.f,b2=0.f,b3=0.f;
    #pragma unroll
    for (int t = 0; t < 8; t++) {
        float4 x = v4[2*t];
        a0 = __fmaf_rn(x.x, x.x, a0); a1 = __fmaf_rn(x.y, x.y, a1);
        a2 = __fmaf_rn(x.z, x.z, a2); a3 = __fmaf_rn(x.w, x.w, a3);
        float4 y = v4[2*t+1];
        b0 = __fmaf_rn(y.x, y.x, b0); b1 = __fmaf_rn(y.y, y.y, b1);
        b2 = __fmaf_rn(y.z, y.z, b2); b3 = __fmaf_rn(y.w, y.w, b3);
    }
    float L0 = a0 + b0, L1 = a1 + b1, L2 = a2 + b2, L3 = a3 + b3;
    return (L0 + L1) + (L2 + L3);
}

// ============================================================
// K1: fused prep (codebook interleave) + norms/contrastive + sampled-zero
//     + 1x1 conv (register-tiled, FMA2, bitwise Eigen order).
// grid 256 x 128 threads.
// ============================================================
__global__ void __launch_bounds__(128) k_conv(const float* __restrict__ zin,
                                              const float* __restrict__ w,
                                              const float* __restrict__ bias,
                                              const float* __restrict__ emb,
                                              float* __restrict__ out) {
    __shared__ unsigned long long ws[CIN * 8];
    __shared__ float bs[16];
    __shared__ float inv_n[32];
    __shared__ float sq[2][EDIM];

    int tid = threadIdx.x;
    int blk = blockIdx.x;

    // ---- prep: pair-interleave codebook (2 elements per thread) ----
    #pragma unroll
    for (int e = 0; e < 2; e++) {
        int o = blk * 256 + e * 128 + tid;
        int P = o >> 7, r = o & 127;
        int k = r >> 1, l = r & 1;
        int t = P >> 6, rem = P & 63;
        int q = rem >> 4, sl = rem & 15;
        int j = t * 128 + 8 * sl + 2 * q + l;
        g_embi[o] = emb[(size_t)j * EDIM + k];
    }
    // zero 'sampled' region (1:1 thread map) + reset completion counter
    out[SAMP_OFF + blk * 128 + tid] = 0.0f;
    if (blk == 0 && tid == 0) g_done = 0;

    // ---- norms + contrastive partials (blocks 0..31) ----
    if (blk < 32) {
        if (tid < 32) {
            int i = blk * 32 + tid;
            float v = sumsq64_p((const float4*)(emb + (size_t)i * EDIM));
            g_se[i] = v;
            inv_n[tid] = 1.0f / sqrtf(v);
        }
        __syncthreads();
        int k = tid & 63, q = tid >> 6;       // q in {0,1}
        float sacc = 0.f;
        #pragma unroll
        for (int i = 0; i < 16; i++) {
            int code = q * 16 + i;
            sacc += emb[(size_t)(blk * 32 + code) * EDIM + k] * inv_n[code];
        }
        sq[q][k] = sacc;
        __syncthreads();
        if (tid < EDIM)
            g_s_part[blk * EDIM + tid] = sq[0][tid] + sq[1][tid];
    }
    __syncthreads();

    // ---- conv ----
    int b = blk >> 3, half = (blk >> 2) & 1, og = blk & 3;
    int obase = og * 16;

    for (int m = tid; m < CIN * 8; m += 128) {
        int c = m >> 3, u = m & 7;
        const float* wp = w + (size_t)(obase + 2 * u) * CIN + c;
        ws[m] = pack2(wp[0], wp[CIN]);
    }
    if (tid < 16) bs[tid] = bias[obase + tid];
    __syncthreads();

    int p0 = half * 512 + tid;
    const float* zp = zin + (size_t)b * CIN * HW + p0;

    unsigned long long acc[8][4];
    #pragma unroll
    for (int u = 0; u < 8; u++)
        #pragma unroll
        for (int j = 0; j < 4; j++) acc[u][j] = 0ULL;

    float zn[4][8];
    #pragma unroll
    for (int j = 0; j < 4; j++)
        #pragma unroll
        for (int i = 0; i < 8; i++)
            zn[j][i] = zp[(size_t)i * HW + 128 * j];

    const ulonglong2* ws2 = (const ulonglong2*)ws;
    for (int ch = 0; ch < 32; ch++) {
        float zc[4][8];
        #pragma unroll
        for (int j = 0; j < 4; j++)
            #pragma unroll
            for (int i = 0; i < 8; i++) zc[j][i] = zn[j][i];
        if (ch < 31) {
            #pragma unroll
            for (int j = 0; j < 4; j++)
                #pragma unroll
                for (int i = 0; i < 8; i++)
                    zn[j][i] = zp[(size_t)((ch + 1) * 8 + i) * HW + 128 * j];
        }
        #pragma unroll
        for (int cc = 0; cc < 8; cc++) {
            int c = ch * 8 + cc;
            unsigned long long zz[4];
            #pragma unroll
            for (int j = 0; j < 4; j++) zz[j] = dupf(zc[j][cc]);
            const ulonglong2* wrow = ws2 + c * 4;
            #pragma unroll
            for (int uu = 0; uu < 4; uu++) {
                ulonglong2 wp = wrow[uu];
                #pragma unroll
                for (int j = 0; j < 4; j++) {
                    fma2(acc[2*uu][j],     zz[j], wp.x);
                    fma2(acc[2*uu + 1][j], zz[j], wp.y);
                }
            }
        }
    }

    float* zo = g_z + (size_t)b * COUT * HW;
    #pragma unroll
    for (int u = 0; u < 8; u++) {
        int o = obase + 2 * u;
        #pragma unroll
        for (int j = 0; j < 4; j++) {
            float lo, hi;
            unpack2(lo, hi, acc[u][j]);
            zo[(size_t)o * HW + p0 + 128 * j]       = lo + bs[2*u];
            zo[(size_t)(o + 1) * HW + p0 + 128 * j] = hi + bs[2*u + 1];
        }
    }
}

// ============================================================
// K2: fused distance+argmin + scatter + loss (last-block finalize).
// 7 rows x 4 code-pairs per thread, 112 rows/block, grid 293,
// double-buffered e tiles. d_j = fl( fl(Sz+Se_j) - 2*dot_j ),
// dot = in-order 64-term FMA chain per lane.
// ============================================================
__global__ void __launch_bounds__(256, 2) k_argmin(float* __restrict__ out,
                                                   const float* __restrict__ emb) {
    extern __shared__ __align__(16) char smem[];
    float4* zs4  = (float4*)smem;                  // [112][17]
    float4* es4  = zs4 + ZS_F4;                    // [2][64 pair-rows][33]
    float*  Sz_s = (float*)(es4 + 2 * ES_F4);      // [112]
    float*  se_s = Sz_s + ROWS_BLK;                // [2][128]
    float*  red  = se_s + 256;                     // [256]
    __shared__ int    is_last;
    __shared__ double rd[256];
    __shared__ float  sv[EDIM];

    int tid = threadIdx.x;
    int s   = tid & 15;                            // code sublane 0..15
    int g   = tid >> 4;                            // row group 0..15
    int row0 = blockIdx.x * ROWS_BLK;

    // stage z rows (clamped for last block) + e tile 0 + se tile 0
    {
        const float4* zall = (const float4*)g_z;
        #pragma unroll
        for (int j = 0; j < RPT; j++) {
            int idx = tid + 256 * j;
            int r = idx >> 4, k4 = idx & 15;
            int grow = row0 + r;
            if (grow > NROWS - 1) grow = NROWS - 1;
            zs4[r * 17 + k4] = zall[(size_t)grow * 16 + k4];
        }
        const float4* src = (const float4*)g_embi;
        #pragma unroll
        for (int j = 0; j < 8; j++) {
            int idx = tid + 256 * j;
            int pr = idx >> 5, wv = idx & 31;
            es4[pr * 33 + wv] = src[idx];
        }
        if (tid < CODE_TILE) se_s[tid] = g_se[tid];
    }
    __syncthreads();
    if (tid < ROWS_BLK)
        Sz_s[tid] = sumsq64_p(zs4 + tid * 17);
    __syncthreads();

    float best[RPT];
    int   bi[RPT];
    #pragma unroll
    for (int i = 0; i < RPT; i++) { best[i] = 3.4e38f; bi[i] = 0; }

    const float4* gsrc = (const float4*)g_embi;
    const float2* zb = ((const float2*)zs4) + g * 34;

    for (int t = 0; t < TILES; t++) {
        int cur = t & 1, nxt = 1 - cur;

        if (t + 1 < TILES) {
            const float4* src = gsrc + (size_t)(t + 1) * 2048;
            #pragma unroll
            for (int j = 0; j < 8; j++) {
                int idx = tid + 256 * j;
                int pr = idx >> 5, wv = idx & 31;
                es4[nxt * ES_F4 + pr * 33 + wv] = src[idx];
            }
            if (tid < CODE_TILE)
                se_s[nxt * 128 + tid] = g_se[(t + 1) * CODE_TILE + tid];
        }

        unsigned long long acc[RPT][4];
        #pragma unroll
        for (int i = 0; i < RPT; i++)
            #pragma unroll
            for (int q = 0; q < 4; q++) acc[i][q] = 0ULL;

        const ulonglong2* ebase = ((const ulonglong2*)(es4 + cur * ES_F4)) + s * 33;

        #pragma unroll 4
        for (int k4 = 0; k4 < 16; k4++) {
            unsigned long long zx[RPT], zy[RPT];
            // half A: dims 4k4, 4k4+1
            #pragma unroll
            for (int i = 0; i < RPT; i++) {
                float2 h = zb[544 * i + 2 * k4];
                zx[i] = dupf(h.x); zy[i] = dupf(h.y);
            }
            #pragma unroll
            for (int q = 0; q < 4; q++) {
                ulonglong2 e01 = ebase[q * 528 + 2 * k4];
                #pragma unroll
                for (int i = 0; i < RPT; i++) {
                    fma2(acc[i][q], zx[i], e01.x);
                    fma2(acc[i][q], zy[i], e01.y);
                }
            }
            // half B: dims 4k4+2, 4k4+3
            #pragma unroll
            for (int i = 0; i < RPT; i++) {
                float2 h = zb[544 * i + 2 * k4 + 1];
                zx[i] = dupf(h.x); zy[i] = dupf(h.y);
            }
            #pragma unroll
            for (int q = 0; q < 4; q++) {
                ulonglong2 e23 = ebase[q * 528 + 2 * k4 + 1];
                #pragma unroll
                for (int i = 0; i < RPT; i++) {
                    fma2(acc[i][q], zx[i], e23.x);
                    fma2(acc[i][q], zy[i], e23.y);
                }
            }
        }

        // eval: per row, q ascending -> codes 8s+2q, 8s+2q+1 ascending
        #pragma unroll
        for (int q = 0; q < 4; q++) {
            int jlo = 8 * s + 2 * q, jhi = jlo + 1;
            float selo = se_s[cur * 128 + jlo], sehi = se_s[cur * 128 + jhi];
            #pragma unroll
            for (int i = 0; i < RPT; i++) {
                float Szv = Sz_s[g + 16 * i];
                float dlo, dhi;
                unpack2(dlo, dhi, acc[i][q]);
                float dv = __fmaf_rn(-2.0f, dlo, Szv + selo);
                if (dv < best[i]) { best[i] = dv; bi[i] = t * CODE_TILE + jlo; }
                float dw = __fmaf_rn(-2.0f, dhi, Szv + sehi);
                if (dw < best[i]) { best[i] = dw; bi[i] = t * CODE_TILE + jhi; }
            }
        }
        __syncthreads();
    }

    // lexicographic merge across the 16 sublanes (per row)
    unsigned m = 0xffffffffu;
    #pragma unroll
    for (int i = 0; i < RPT; i++) {
        float bv = best[i]; int bj = bi[i];
        #pragma unroll
        for (int off = 8; off > 0; off >>= 1) {
            float ob = __shfl_down_sync(m, bv, off, 16);
            int   oi = __shfl_down_sync(m, bj, off, 16);
            if (ob < bv || (ob == bv && oi < bj)) { bv = ob; bj = oi; }
        }
        bj = __shfl_sync(m, bj, 0, 16);
        bi[i] = bj;
    }

    // epilogue per valid row: idx/min_idx/scatter, z_q_st, loss partial
    float lacc = 0.f;
    #pragma unroll
    for (int i = 0; i < RPT; i++) {
        int rl = g + 16 * i;
        int row = row0 + rl;
        if (row < NROWS) {
            int bj = bi[i];
            if (s == 0) {
                g_idx[row] = bj;
                out[MIDX_OFF + row] = (float)bj;
                out[SAMP_OFF + bj] = 1.0f;   // sampled scatter (zeroed by k_conv)
            }
            float4 e = ((const float4*)(emb + (size_t)bj * EDIM))[s];
            float4 z = zs4[rl * 17 + s];
            float dx = e.x - z.x, dy = e.y - z.y, dz = e.z - z.z, dw = e.w - z.w;
            float4 o;
            o.x = z.x + dx; o.y = z.y + dy; o.z = z.z + dz; o.w = z.w + dw;
            ((float4*)(out + ZQ_OFF + (size_t)row * EDIM))[s] = o;
            lacc += dx*dx + dy*dy + dz*dz + dw*dw;
        }
    }
    red[tid] = lacc;
    __syncthreads();
    #pragma unroll
    for (int st = 128; st > 0; st >>= 1) {
        if (tid < st) red[tid] += red[tid + st];
        __syncthreads();
    }
    if (tid == 0) {
        g_loss_part[blockIdx.x] = red[0];
        __threadfence();
        int old = atomicAdd(&g_done, 1);
        is_last = (old == NBLK - 1);
    }
    __syncthreads();

    // last block to finish reduces the loss scalar (fixed order -> deterministic)
    if (is_last) {
        __threadfence();
        double a = (double)g_loss_part[tid];
        if (tid + 256 < NBLK) a += (double)g_loss_part[tid + 256];
        rd[tid] = a;
        if (tid < EDIM) {
            float v = 0.f;
            #pragma unroll
            for (int j = 0; j < 32; j++) v += g_s_part[j * EDIM + tid];
            sv[tid] = v * v;
        }
        __syncthreads();
        #pragma unroll
        for (int st = 128; st > 0; st >>= 1) {
            if (tid < st) rd[tid] += rd[tid + st];
            __syncthreads();
        }
        if (tid == 0) {
            float c = 0.f;
            for (int j = 0; j < EDIM; j++) c += sv[j];
            out[LOSS_OFF] = (float)(1.25 * (rd[0] / (double)ZLEN))
                          + c / ((float)NE * (float)NE);
        }
    }
}

// ============================================================
extern "C" void kernel_launch(void* const* d_in, const int* in_sizes, int n_in,
                              void* d_out, int out_size) {
    const float* z_    = (const float*)d_in[0];
    const float* convw = (const float*)d_in[1];
    const float* convb = (const float*)d_in[2];
    const float* emb   = (const float*)d_in[3];
    float* out = (float*)d_out;

    cudaFuncSetAttribute(k_argmin, cudaFuncAttributeMaxDynamicSharedMemorySize,
                         SMEM_ARGMIN);

    k_conv<<<256, 128>>>(z_, convw, convb, emb, out);
    k_argmin<<<NBLK, 256, SMEM_ARGMIN>>>(out, emb);
}